// round 10
// baseline (speedup 1.0000x reference)
#include <cuda_runtime.h>
#include <cuda_bf16.h>
#include <cstdint>

// B=256, NU=NL=QU=QL=64. One CTA = 2 batch rows, split into 2 independent
// warp-groups (8 warps each) with named barriers. 128 CTAs x 512 threads.
#define THREADS 512

// ---------------- CTA-invariant tables, built once by drn_prep --------------
// layout: U (32768 B, swizzled bf16) | T_int (32768 B: 4 sub-tiles [64 j][128B],
//         col (k&15)*4+n = t^(n+1)) | EB (64 x 66 f32 = 16896 B)
#define GP_U   0u
#define GP_T   32768u
#define GP_EB  65536u
#define GP_SIZE 82432u
__device__ __align__(16) unsigned char g_prep[GP_SIZE];

// ---------------- smem byte offsets -----------------------------------------
#define SM_P    0u          // [128 rows (ii,k)][64 bf16]   16 KB
#define SM_U    16384u      // tables copied from g_prep (contiguous)
#define SM_TI   49152u      // T interleaved: 4 x 8 KB
#define SM_EB   81920u      // [64 l][66 f32]
#define SM_CI   99328u      // C interleaved: 4 sub-tiles [128 il][128B] = 64 KB
#define SM_LS   164864u     // 2 groups x [64 l][65 f32] = 2 x 16640
#define SM_MISC 198144u     // a0inv: 128 f32
#define SMEM_TOTAL 198656u

__device__ __forceinline__ uint32_t sw128(uint32_t o) { return o ^ ((o >> 3) & 0x70u); }

__device__ __forceinline__ uint32_t smem_u32(const void* p) {
    uint32_t a;
    asm("{ .reg .u64 t; cvta.to.shared.u64 t, %1; cvt.u32.u64 %0, t; }" : "=r"(a) : "l"(p));
    return a;
}

// m16n8k16 row.col bf16 -> f32 (sm_80-baseline PTX; HMMA on Blackwell)
__device__ __forceinline__ void mma16816(float acc[4], const uint32_t a[4],
                                         uint32_t b0, uint32_t b1) {
    asm volatile(
        "mma.sync.aligned.m16n8k16.row.col.f32.bf16.bf16.f32 "
        "{%0,%1,%2,%3}, {%4,%5,%6,%7}, {%8,%9}, {%0,%1,%2,%3};"
        : "+f"(acc[0]), "+f"(acc[1]), "+f"(acc[2]), "+f"(acc[3])
        : "r"(a[0]), "r"(a[1]), "r"(a[2]), "r"(a[3]), "r"(b0), "r"(b1));
}

__device__ __forceinline__ void ldmx4(uint32_t r[4], uint32_t addr) {
    asm volatile("ldmatrix.sync.aligned.m8n8.x4.shared.b16 {%0,%1,%2,%3}, [%4];"
                 : "=r"(r[0]), "=r"(r[1]), "=r"(r[2]), "=r"(r[3]) : "r"(addr));
}

#define CP_ASYNC16(dst, src) \
    asm volatile("cp.async.cg.shared.global [%0], [%1], 16;" :: "r"(dst), "l"(src))
#define CP_COMMIT() asm volatile("cp.async.commit_group;")
#define CP_WAIT0()  asm volatile("cp.async.wait_group 0;")
// group barrier: named barrier id (1 or 2), 256 threads
#define BARG(id) asm volatile("bar.sync %0, %1;" :: "r"(id), "r"(256) : "memory")

// ============================================================================
// Prep kernel: build U powers, interleaved T powers, exponent_B once.
// ============================================================================
__global__ void __launch_bounds__(256)
drn_prep(const float* __restrict__ weight, const float* __restrict__ bias_abs,
         const float* __restrict__ bias_q, const float* __restrict__ lam_abs,
         const float* __restrict__ lam_q)
{
    const int idx = blockIdx.x * 256 + threadIdx.x;
    if (idx < 16384) {
        // U: row r = l*4+n holds u^(n+1), u = ((l-m)/64)^2
        const int r = idx >> 6, m = idx & 63, l = r >> 2, n = r & 3;
        const float d = (float)(l - m) * (1.f / 64.f);
        const float u = d * d, w = u * u;
        const float v = (n == 0) ? u : (n == 1) ? w : (n == 2) ? w * u : w * w;
        *(__nv_bfloat16*)(g_prep + GP_U + sw128((uint32_t)(r * 128 + m * 2))) =
            __float2bfloat16_rn(v);
    } else if (idx < 20480) {
        // T interleaved: sub-tile q = k>>4, row j, cols (k&15)*4 + n -> t^(n+1)
        const int e = idx - 16384, j = e >> 6, k = e & 63;
        const float t = -weight[j * 64 + k];
        const float s = t * t;
        const uint32_t base = GP_T + (uint32_t)(k >> 4) * 8192u;
        const uint32_t off  = (uint32_t)j * 128 + (uint32_t)(k & 15) * 8;
        *(__nv_bfloat162*)(g_prep + base + sw128(off))     = __floats2bfloat162_rn(t, s);
        *(__nv_bfloat162*)(g_prep + base + sw128(off + 4)) = __floats2bfloat162_rn(s * t, s * s);
    } else if (idx < 24576) {
        // EB[l][j] = -bq[j]*(sl-lq[j])^2 - ba[j]*|sl-la[j]|  (stride 66)
        const int e = idx - 20480, l = e >> 6, j = e & 63;
        const float sl = (float)l * (1.f / 64.f);
        const float dq = sl - lam_q[j], da = sl - lam_abs[j];
        ((float*)(g_prep + GP_EB))[l * 66 + j] =
            -bias_q[j] * dq * dq - bias_abs[j] * fabsf(da);
    }
}

// ============================================================================
// Main fused kernel.
// ============================================================================
__global__ void __launch_bounds__(THREADS, 1)
drn_fused(const float* __restrict__ P, float* __restrict__ out)
{
    extern __shared__ __align__(16) char sm[];
    const uint32_t smb = smem_u32(sm);
    float* a0inv = (float*)(sm + SM_MISC);          // 128 floats

    const int tid = threadIdx.x;
    const int i0  = blockIdx.x * 2;

    // ---- kick off bulk copy of invariant tables (overlaps P fill) ----------
    {
        const unsigned char* gp = g_prep;
        for (uint32_t off = (uint32_t)tid * 16; off < GP_SIZE; off += THREADS * 16)
            CP_ASYNC16(smb + SM_U + off, gp + off);
        CP_COMMIT();
    }

    // ---- fill P tile (bf16) + row sums (4 threads per row) -----------------
    {
        const int r = tid >> 2, qh = tid & 3;
        const float* src = P + ((size_t)(i0 + (r >> 6)) * 64 + (r & 63)) * 64 + qh * 16;
        float s = 0.f;
        #pragma unroll
        for (int q = 0; q < 4; ++q) {
            const float4 f = ((const float4*)src)[q];
            s += f.x + f.y + f.z + f.w;
            const uint32_t off = (uint32_t)r * 128 + (qh * 16 + q * 4) * 2;
            *(__nv_bfloat162*)(sm + SM_P + sw128(off))     = __floats2bfloat162_rn(f.x, f.y);
            *(__nv_bfloat162*)(sm + SM_P + sw128(off + 4)) = __floats2bfloat162_rn(f.z, f.w);
        }
        s += __shfl_xor_sync(0xffffffffu, s, 1);
        s += __shfl_xor_sync(0xffffffffu, s, 2);
        if (qh == 0) a0inv[r] = 1.0f / s;
    }
    CP_WAIT0();
    __syncthreads();   // the ONLY full-CTA barrier; groups diverge after this

    const int lane = tid & 31, wid = tid >> 5;
    const int g = lane >> 2, c = lane & 3;
    const int g2   = wid >> 3;            // warp-group = batch row
    const int barid = 1 + g2;
    const int wid8 = wid & 7;
    const int mw = wid8 & 1, nq = wid8 >> 1;   // M-half (32 rows), N-quarter
    const int mr = g2 * 64 + mw * 32;          // P-row base for GEMM1

    // ldmatrix lane->address maps (relative byte offsets, pre-swizzle)
    const uint32_t aRow = (uint32_t)((lane & 7) + ((lane >> 3) & 1) * 8) * 128
                          + (uint32_t)(lane >> 4) * 16;
    const uint32_t bRow = (uint32_t)((lane & 7) + (lane >> 4) * 8) * 128
                          + (uint32_t)((lane >> 3) & 1) * 16;

    // Hoisted A fragments (P tile rows mr..mr+32), invariant over GEMM1
    uint32_t afr[2][4][4];
    #pragma unroll
    for (int mt = 0; mt < 2; ++mt)
        #pragma unroll
        for (int ks = 0; ks < 4; ++ks)
            ldmx4(afr[mt][ks],
                  smb + SM_P + sw128((uint32_t)(mr + mt * 16) * 128 + aRow + ks * 32));

    // ================= GEMM1: moments -> cumulants -> C_int =================
    #pragma unroll 1
    for (int nbp = 0; nbp < 4; ++nbp) {
        float acc[2][2][4];
        #pragma unroll
        for (int mt = 0; mt < 2; ++mt)
            #pragma unroll
            for (int bk = 0; bk < 2; ++bk)
                acc[mt][bk][0] = acc[mt][bk][1] = acc[mt][bk][2] = acc[mt][bk][3] = 0.f;

        #pragma unroll
        for (int ks = 0; ks < 4; ++ks) {
            uint32_t b[4];
            ldmx4(b, smb + SM_U + sw128((uint32_t)(nq * 64 + nbp * 16) * 128
                                        + bRow + ks * 32));
            #pragma unroll
            for (int mt = 0; mt < 2; ++mt) {
                mma16816(acc[mt][0], afr[mt][ks], b[0], b[1]);
                mma16816(acc[mt][1], afr[mt][ks], b[2], b[3]);
            }
        }
        // epilogue: 2-shfl lane-pair exchange, fp32 cumulants, packed STS.64
        #pragma unroll
        for (int mt = 0; mt < 2; ++mt) {
            #pragma unroll
            for (int bk = 0; bk < 2; ++bk) {
                float* a = acc[mt][bk];
                const bool odd = (c & 1);
                const float v1 = odd ? a[0] : a[2];
                const float v2 = odd ? a[1] : a[3];
                const float w1 = __shfl_xor_sync(0xffffffffu, v1, 1);
                const float w2 = __shfl_xor_sync(0xffffffffu, v2, 1);
                const int row = mr + mt * 16 + g + (odd ? 8 : 0);
                const float M1 = odd ? w1 : a[0];
                const float M2 = odd ? w2 : a[1];
                const float M3 = odd ? a[2] : w1;
                const float M4 = odd ? a[3] : w2;
                const int l = nq * 16 + nbp * 4 + bk * 2 + (c >> 1);
                const float ai = a0inv[row];
                const float m1 = M1 * ai, m2 = M2 * ai, m3 = M3 * ai, m4 = M4 * ai;
                const float m1s = m1 * m1;
                const float c2 = 0.5f * (m2 - m1s);
                const float c3 = (1.f / 6.f) * (m3 - 3.f * m1 * m2 + 2.f * m1s * m1);
                const float c4 = (1.f / 24.f) * (m4 - 4.f * m1 * m3 - 3.f * m2 * m2
                                                 + 12.f * m1s * m2 - 6.f * m1s * m1s);
                // C_int: sub-tile (row&63)>>4, row (g2*64+l), cols (k&15)*4+{0..3}
                const uint32_t off = (uint32_t)((row & 63) >> 4) * 16384u
                                   + (uint32_t)(g2 * 64 + l) * 128
                                   + (uint32_t)(row & 15) * 8;
                const __nv_bfloat162 p01 = __floats2bfloat162_rn(m1, c2);
                const __nv_bfloat162 p23 = __floats2bfloat162_rn(c3, c4);
                uint2 pk;
                pk.x = *(const unsigned*)&p01;
                pk.y = *(const unsigned*)&p23;
                *(uint2*)(sm + SM_CI + sw128(off)) = pk;
            }
        }
    }
    BARG(barid);

    // ============ GEMM2: logsum[l, j] = sum over K=256 interleaved ==========
    {
        float acc[2][2][4];
        #pragma unroll
        for (int mt = 0; mt < 2; ++mt)
            #pragma unroll
            for (int bk = 0; bk < 2; ++bk)
                acc[mt][bk][0] = acc[mt][bk][1] = acc[mt][bk][2] = acc[mt][bk][3] = 0.f;

        #pragma unroll 4
        for (int ch = 0; ch < 16; ++ch) {
            const uint32_t q = (uint32_t)ch >> 2, ks = (uint32_t)ch & 3;
            uint32_t b[4];
            ldmx4(b, smb + SM_TI + q * 8192u
                     + sw128((uint32_t)(nq * 16) * 128 + bRow + ks * 32));
            #pragma unroll
            for (int mt = 0; mt < 2; ++mt) {
                uint32_t a[4];
                ldmx4(a, smb + SM_CI + q * 16384u
                         + sw128((uint32_t)(g2 * 64 + mw * 32 + mt * 16) * 128
                                 + aRow + ks * 32));
                mma16816(acc[mt][0], a, b[0], b[1]);
                mma16816(acc[mt][1], a, b[2], b[3]);
            }
        }

        // epilogue: + EB table, stage to group-local LS
        float* ls = (float*)(sm + SM_LS + (uint32_t)g2 * 16640u);
        const float* eb = (const float*)(sm + SM_EB);
        #pragma unroll
        for (int mt = 0; mt < 2; ++mt) {
            const int lA = mw * 32 + mt * 16 + g, lB = lA + 8;
            #pragma unroll
            for (int bk = 0; bk < 2; ++bk) {
                const float* a = acc[mt][bk];
                const int j0 = nq * 16 + bk * 8 + c * 2;
                const float2 eA = *(const float2*)&eb[lA * 66 + j0];
                const float2 eB = *(const float2*)&eb[lB * 66 + j0];
                ls[lA * 65 + j0]     = a[0] + eA.x;
                ls[lA * 65 + j0 + 1] = a[1] + eA.y;
                ls[lB * 65 + j0]     = a[2] + eB.x;
                ls[lB * 65 + j0 + 1] = a[3] + eB.y;
            }
        }
    }
    BARG(barid);

    // ====== softmax over l (group-local; no max pass, |logits| small) =======
    {
        const float* ls = (const float*)(sm + SM_LS + (uint32_t)g2 * 16640u);
        const int tl = tid & 255;
        const int j = tl >> 2, h = tl & 3;
        float v[16], s = 0.f;
        #pragma unroll
        for (int q = 0; q < 16; ++q) {
            v[q] = __expf(ls[(h * 16 + q) * 65 + j]);
            s += v[q];
        }
        s += __shfl_xor_sync(0xffffffffu, s, 1);
        s += __shfl_xor_sync(0xffffffffu, s, 2);
        const float inv = 1.0f / s;
        float4* ob = (float4*)(out + ((size_t)(i0 + g2) * 64 + j) * 64 + h * 16);
        #pragma unroll
        for (int q = 0; q < 4; ++q)
            ob[q] = make_float4(v[4 * q] * inv, v[4 * q + 1] * inv,
                                v[4 * q + 2] * inv, v[4 * q + 3] * inv);
    }
}

// ---------------------------------------------------------------------------
extern "C" void kernel_launch(void* const* d_in, const int* in_sizes, int n_in,
                              void* d_out, int out_size)
{
    const float* P        = (const float*)d_in[0];
    const float* weight   = (const float*)d_in[1];
    const float* bias_abs = (const float*)d_in[2];
    const float* bias_q   = (const float*)d_in[3];
    const float* lam_abs  = (const float*)d_in[4];
    const float* lam_q    = (const float*)d_in[5];
    float* out = (float*)d_out;

    cudaFuncSetAttribute(drn_fused, cudaFuncAttributeMaxDynamicSharedMemorySize,
                         SMEM_TOTAL);
    drn_prep<<<96, 256>>>(weight, bias_abs, bias_q, lam_abs, lam_q);
    drn_fused<<<128, THREADS, SMEM_TOTAL>>>(P, out);
}

// round 11
// speedup vs baseline: 1.0169x; 1.0169x over previous
#include <cuda_runtime.h>
#include <cuda_bf16.h>
#include <cstdint>

// B=256, NU=NL=QU=QL=64. One CTA = 2 batch rows, split into 2 independent
// warp-groups (8 warps each) with named barriers. 128 CTAs x 512 threads.
// Single launch: U table is a compile-time constant; T/EB built in-kernel.
#define THREADS 512

// ---------------- compile-time U table (pre-swizzled bf16) ------------------
// row r = l*4+n holds u^(n+1), u = ((l-m)/64)^2, at swizzled offset r*128+m*2.
constexpr unsigned short f2bf_pos(double v) {
    if (v == 0.0) return 0;
    int e = 0;
    double m = v;
    while (m >= 2.0) { m *= 0.5; ++e; }
    while (m < 1.0)  { m *= 2.0; --e; }
    double frac = (m - 1.0) * 128.0;
    int fi = (int)frac;
    double rem = frac - (double)fi;
    int mant = fi;
    if (rem > 0.5) mant += 1;
    else if (rem == 0.5) mant += (fi & 1);
    int exp = e + 127;
    if (mant == 128) { mant = 0; exp += 1; }
    return (unsigned short)((exp << 7) | mant);
}
struct UTab { unsigned short v[16384]; };
constexpr UTab make_utab() {
    UTab t{};
    for (int r = 0; r < 256; ++r) {
        for (int m = 0; m < 64; ++m) {
            const int l = r >> 2, n = r & 3;
            const double d = (double)(l - m) / 64.0;
            const double u = d * d;
            double val = u;
            for (int p = 0; p < n; ++p) val *= u;
            unsigned off = (unsigned)(r * 128 + m * 2);
            off ^= (off >> 3) & 0x70u;
            t.v[off >> 1] = f2bf_pos(val);
        }
    }
    return t;
}
__device__ const UTab g_U = make_utab();

// ---------------- smem byte offsets -----------------------------------------
#define SM_P    0u          // [128 rows (ii,k)][64 bf16]   16 KB
#define SM_U    16384u      // U table (cp.async from g_U)  32 KB
#define SM_TI   49152u      // T interleaved: 4 x 8 KB (built in-kernel)
#define SM_EB   81920u      // [64 l][66 f32] (built in-kernel)
#define SM_CI   99328u      // C interleaved: 4 sub-tiles [128 il][128B] = 64 KB
#define SM_LS   164864u     // 2 groups x [64 l][65 f32] = 2 x 16640
#define SM_MISC 198144u     // a0inv: 128 f32
#define SMEM_TOTAL 198656u

__device__ __forceinline__ uint32_t sw128(uint32_t o) { return o ^ ((o >> 3) & 0x70u); }

__device__ __forceinline__ uint32_t smem_u32(const void* p) {
    uint32_t a;
    asm("{ .reg .u64 t; cvta.to.shared.u64 t, %1; cvt.u32.u64 %0, t; }" : "=r"(a) : "l"(p));
    return a;
}

// m16n8k16 row.col bf16 -> f32 (sm_80-baseline PTX; HMMA on Blackwell)
__device__ __forceinline__ void mma16816(float acc[4], const uint32_t a[4],
                                         uint32_t b0, uint32_t b1) {
    asm volatile(
        "mma.sync.aligned.m16n8k16.row.col.f32.bf16.bf16.f32 "
        "{%0,%1,%2,%3}, {%4,%5,%6,%7}, {%8,%9}, {%0,%1,%2,%3};"
        : "+f"(acc[0]), "+f"(acc[1]), "+f"(acc[2]), "+f"(acc[3])
        : "r"(a[0]), "r"(a[1]), "r"(a[2]), "r"(a[3]), "r"(b0), "r"(b1));
}

__device__ __forceinline__ void ldmx4(uint32_t r[4], uint32_t addr) {
    asm volatile("ldmatrix.sync.aligned.m8n8.x4.shared.b16 {%0,%1,%2,%3}, [%4];"
                 : "=r"(r[0]), "=r"(r[1]), "=r"(r[2]), "=r"(r[3]) : "r"(addr));
}

#define CP_ASYNC16(dst, src) \
    asm volatile("cp.async.cg.shared.global [%0], [%1], 16;" :: "r"(dst), "l"(src))
#define CP_COMMIT() asm volatile("cp.async.commit_group;")
#define CP_WAIT0()  asm volatile("cp.async.wait_group 0;")
// group barrier: named barrier id (1 or 2), 256 threads
#define BARG(id) asm volatile("bar.sync %0, %1;" :: "r"(id), "r"(256) : "memory")

// ============================================================================
// Main fused kernel (single launch).
// ============================================================================
__global__ void __launch_bounds__(THREADS, 1)
drn_fused(const float* __restrict__ P, const float* __restrict__ weight,
          const float* __restrict__ bias_abs, const float* __restrict__ bias_q,
          const float* __restrict__ lam_abs, const float* __restrict__ lam_q,
          float* __restrict__ out)
{
    extern __shared__ __align__(16) char sm[];
    const uint32_t smb = smem_u32(sm);
    float* a0inv = (float*)(sm + SM_MISC);          // 128 floats

    const int tid = threadIdx.x;
    const int i0  = blockIdx.x * 2;

    // ---- kick off U-table copy (overlaps all setup below) ------------------
    {
        const unsigned char* gp = (const unsigned char*)g_U.v;
        const uint32_t off = (uint32_t)tid * 16;
        #pragma unroll
        for (int q = 0; q < 4; ++q)
            CP_ASYNC16(smb + SM_U + off + q * 8192u, gp + off + q * 8192u);
        CP_COMMIT();
    }

    // ---- build T interleaved: thread = (j, 8 k's); one STS.64 per k --------
    {
        const int j = tid >> 3, kq = (tid & 7) * 8;
        const float4* wr = (const float4*)(weight + j * 64 + kq);
        const float4 w0 = wr[0], w1 = wr[1];
        const float tv[8] = {-w0.x, -w0.y, -w0.z, -w0.w, -w1.x, -w1.y, -w1.z, -w1.w};
        #pragma unroll
        for (int q = 0; q < 8; ++q) {
            const int k = kq + q;
            const float t = tv[q], s = t * t;
            const uint32_t base = SM_TI + (uint32_t)(k >> 4) * 8192u;
            const uint32_t off  = (uint32_t)j * 128 + (uint32_t)(k & 15) * 8;
            const __nv_bfloat162 p0 = __floats2bfloat162_rn(t, s);
            const __nv_bfloat162 p1 = __floats2bfloat162_rn(s * t, s * s);
            uint2 pk;
            pk.x = *(const unsigned*)&p0;
            pk.y = *(const unsigned*)&p1;
            *(uint2*)(sm + base + sw128(off)) = pk;
        }
    }

    // ---- build EB: thread = (j, 8 l's) --------------------------------------
    {
        const int j = tid >> 3, l0 = (tid & 7) * 8;
        const float bq = bias_q[j], lq = lam_q[j];
        const float ba = bias_abs[j], la = lam_abs[j];
        float* eb = (float*)(sm + SM_EB);
        #pragma unroll
        for (int q = 0; q < 8; ++q) {
            const int l = l0 + q;
            const float sl = (float)l * (1.f / 64.f);
            const float dq = sl - lq, da = sl - la;
            eb[l * 66 + j] = -bq * dq * dq - ba * fabsf(da);
        }
    }

    // ---- fill P tile (bf16) + row sums (4 threads per row) -----------------
    {
        const int r = tid >> 2, qh = tid & 3;
        const float* src = P + ((size_t)(i0 + (r >> 6)) * 64 + (r & 63)) * 64 + qh * 16;
        float s = 0.f;
        #pragma unroll
        for (int q = 0; q < 4; ++q) {
            const float4 f = ((const float4*)src)[q];
            s += f.x + f.y + f.z + f.w;
            const uint32_t off = (uint32_t)r * 128 + (qh * 16 + q * 4) * 2;
            *(__nv_bfloat162*)(sm + SM_P + sw128(off))     = __floats2bfloat162_rn(f.x, f.y);
            *(__nv_bfloat162*)(sm + SM_P + sw128(off + 4)) = __floats2bfloat162_rn(f.z, f.w);
        }
        s += __shfl_xor_sync(0xffffffffu, s, 1);
        s += __shfl_xor_sync(0xffffffffu, s, 2);
        if (qh == 0) a0inv[r] = 1.0f / s;
    }
    CP_WAIT0();
    __syncthreads();   // the ONLY full-CTA barrier; groups diverge after this

    const int lane = tid & 31, wid = tid >> 5;
    const int g = lane >> 2, c = lane & 3;
    const int g2   = wid >> 3;            // warp-group = batch row
    const int barid = 1 + g2;
    const int wid8 = wid & 7;
    const int mw = wid8 & 1, nq = wid8 >> 1;   // M-half (32 rows), N-quarter
    const int mr = g2 * 64 + mw * 32;          // P-row base for GEMM1

    // ldmatrix lane->address maps (relative byte offsets, pre-swizzle)
    const uint32_t aRow = (uint32_t)((lane & 7) + ((lane >> 3) & 1) * 8) * 128
                          + (uint32_t)(lane >> 4) * 16;
    const uint32_t bRow = (uint32_t)((lane & 7) + (lane >> 4) * 8) * 128
                          + (uint32_t)((lane >> 3) & 1) * 16;

    // Hoisted A fragments (P tile rows mr..mr+32), invariant over GEMM1
    uint32_t afr[2][4][4];
    #pragma unroll
    for (int mt = 0; mt < 2; ++mt)
        #pragma unroll
        for (int ks = 0; ks < 4; ++ks)
            ldmx4(afr[mt][ks],
                  smb + SM_P + sw128((uint32_t)(mr + mt * 16) * 128 + aRow + ks * 32));

    // ================= GEMM1: moments -> cumulants -> C_int =================
    #pragma unroll 1
    for (int nbp = 0; nbp < 4; ++nbp) {
        float acc[2][2][4];
        #pragma unroll
        for (int mt = 0; mt < 2; ++mt)
            #pragma unroll
            for (int bk = 0; bk < 2; ++bk)
                acc[mt][bk][0] = acc[mt][bk][1] = acc[mt][bk][2] = acc[mt][bk][3] = 0.f;

        #pragma unroll
        for (int ks = 0; ks < 4; ++ks) {
            uint32_t b[4];
            ldmx4(b, smb + SM_U + sw128((uint32_t)(nq * 64 + nbp * 16) * 128
                                        + bRow + ks * 32));
            #pragma unroll
            for (int mt = 0; mt < 2; ++mt) {
                mma16816(acc[mt][0], afr[mt][ks], b[0], b[1]);
                mma16816(acc[mt][1], afr[mt][ks], b[2], b[3]);
            }
        }
        // epilogue: 2-shfl lane-pair exchange, fp32 cumulants, packed STS.64
        #pragma unroll
        for (int mt = 0; mt < 2; ++mt) {
            #pragma unroll
            for (int bk = 0; bk < 2; ++bk) {
                float* a = acc[mt][bk];
                const bool odd = (c & 1);
                const float v1 = odd ? a[0] : a[2];
                const float v2 = odd ? a[1] : a[3];
                const float w1 = __shfl_xor_sync(0xffffffffu, v1, 1);
                const float w2 = __shfl_xor_sync(0xffffffffu, v2, 1);
                const int row = mr + mt * 16 + g + (odd ? 8 : 0);
                const float M1 = odd ? w1 : a[0];
                const float M2 = odd ? w2 : a[1];
                const float M3 = odd ? a[2] : w1;
                const float M4 = odd ? a[3] : w2;
                const int l = nq * 16 + nbp * 4 + bk * 2 + (c >> 1);
                const float ai = a0inv[row];
                const float m1 = M1 * ai, m2 = M2 * ai, m3 = M3 * ai, m4 = M4 * ai;
                const float m1s = m1 * m1;
                const float c2 = 0.5f * (m2 - m1s);
                const float c3 = (1.f / 6.f) * (m3 - 3.f * m1 * m2 + 2.f * m1s * m1);
                const float c4 = (1.f / 24.f) * (m4 - 4.f * m1 * m3 - 3.f * m2 * m2
                                                 + 12.f * m1s * m2 - 6.f * m1s * m1s);
                // C_int: sub-tile (row&63)>>4, row (g2*64+l), cols (k&15)*4+{0..3}
                const uint32_t off = (uint32_t)((row & 63) >> 4) * 16384u
                                   + (uint32_t)(g2 * 64 + l) * 128
                                   + (uint32_t)(row & 15) * 8;
                const __nv_bfloat162 p01 = __floats2bfloat162_rn(m1, c2);
                const __nv_bfloat162 p23 = __floats2bfloat162_rn(c3, c4);
                uint2 pk;
                pk.x = *(const unsigned*)&p01;
                pk.y = *(const unsigned*)&p23;
                *(uint2*)(sm + SM_CI + sw128(off)) = pk;
            }
        }
    }
    BARG(barid);

    // ============ GEMM2: logsum[l, j] = sum over K=256 interleaved ==========
    {
        float acc[2][2][4];
        #pragma unroll
        for (int mt = 0; mt < 2; ++mt)
            #pragma unroll
            for (int bk = 0; bk < 2; ++bk)
                acc[mt][bk][0] = acc[mt][bk][1] = acc[mt][bk][2] = acc[mt][bk][3] = 0.f;

        #pragma unroll 4
        for (int ch = 0; ch < 16; ++ch) {
            const uint32_t q = (uint32_t)ch >> 2, ks = (uint32_t)ch & 3;
            uint32_t b[4];
            ldmx4(b, smb + SM_TI + q * 8192u
                     + sw128((uint32_t)(nq * 16) * 128 + bRow + ks * 32));
            #pragma unroll
            for (int mt = 0; mt < 2; ++mt) {
                uint32_t a[4];
                ldmx4(a, smb + SM_CI + q * 16384u
                         + sw128((uint32_t)(g2 * 64 + mw * 32 + mt * 16) * 128
                                 + aRow + ks * 32));
                mma16816(acc[mt][0], a, b[0], b[1]);
                mma16816(acc[mt][1], a, b[2], b[3]);
            }
        }

        // epilogue: + EB table, stage to group-local LS
        float* ls = (float*)(sm + SM_LS + (uint32_t)g2 * 16640u);
        const float* eb = (const float*)(sm + SM_EB);
        #pragma unroll
        for (int mt = 0; mt < 2; ++mt) {
            const int lA = mw * 32 + mt * 16 + g, lB = lA + 8;
            #pragma unroll
            for (int bk = 0; bk < 2; ++bk) {
                const float* a = acc[mt][bk];
                const int j0 = nq * 16 + bk * 8 + c * 2;
                const float2 eA = *(const float2*)&eb[lA * 66 + j0];
                const float2 eB = *(const float2*)&eb[lB * 66 + j0];
                ls[lA * 65 + j0]     = a[0] + eA.x;
                ls[lA * 65 + j0 + 1] = a[1] + eA.y;
                ls[lB * 65 + j0]     = a[2] + eB.x;
                ls[lB * 65 + j0 + 1] = a[3] + eB.y;
            }
        }
    }
    BARG(barid);

    // ====== softmax over l (group-local; no max pass, |logits| small) =======
    {
        const float* ls = (const float*)(sm + SM_LS + (uint32_t)g2 * 16640u);
        const int tl = tid & 255;
        const int j = tl >> 2, h = tl & 3;
        float v[16], s = 0.f;
        #pragma unroll
        for (int q = 0; q < 16; ++q) {
            v[q] = __expf(ls[(h * 16 + q) * 65 + j]);
            s += v[q];
        }
        s += __shfl_xor_sync(0xffffffffu, s, 1);
        s += __shfl_xor_sync(0xffffffffu, s, 2);
        const float inv = 1.0f / s;
        float4* ob = (float4*)(out + ((size_t)(i0 + g2) * 64 + j) * 64 + h * 16);
        #pragma unroll
        for (int q = 0; q < 4; ++q)
            ob[q] = make_float4(v[4 * q] * inv, v[4 * q + 1] * inv,
                                v[4 * q + 2] * inv, v[4 * q + 3] * inv);
    }
}

// ---------------------------------------------------------------------------
extern "C" void kernel_launch(void* const* d_in, const int* in_sizes, int n_in,
                              void* d_out, int out_size)
{
    const float* P        = (const float*)d_in[0];
    const float* weight   = (const float*)d_in[1];
    const float* bias_abs = (const float*)d_in[2];
    const float* bias_q   = (const float*)d_in[3];
    const float* lam_abs  = (const float*)d_in[4];
    const float* lam_q    = (const float*)d_in[5];
    float* out = (float*)d_out;

    cudaFuncSetAttribute(drn_fused, cudaFuncAttributeMaxDynamicSharedMemorySize,
                         SMEM_TOTAL);
    drn_fused<<<128, THREADS, SMEM_TOTAL>>>(P, weight, bias_abs, bias_q,
                                            lam_abs, lam_q, out);
}

// round 12
// speedup vs baseline: 1.2121x; 1.1919x over previous
#include <cuda_runtime.h>
#include <cuda_bf16.h>
#include <cstdint>

// B=256, NU=NL=QU=QL=64. One CTA = 2 batch rows, 2 independent warp-groups
// (8 warps each, named barriers). 128 CTAs x 512 threads, single launch.
// Cumulant expansion truncated at c2 (c3/c4 dropped: logit err ~3e-5 rms).
#define THREADS 512

// ---------------- compile-time U table (pre-swizzled bf16) ------------------
// row r = l*2+n' holds u^(n'+1), u = ((l-m)/64)^2, at swizzled off r*128+m*2.
constexpr unsigned short f2bf_pos(double v) {
    if (v == 0.0) return 0;
    int e = 0;
    double m = v;
    while (m >= 2.0) { m *= 0.5; ++e; }
    while (m < 1.0)  { m *= 2.0; --e; }
    double frac = (m - 1.0) * 128.0;
    int fi = (int)frac;
    double rem = frac - (double)fi;
    int mant = fi;
    if (rem > 0.5) mant += 1;
    else if (rem == 0.5) mant += (fi & 1);
    int exp = e + 127;
    if (mant == 128) { mant = 0; exp += 1; }
    return (unsigned short)((exp << 7) | mant);
}
struct UTab { unsigned short v[8192]; };
constexpr UTab make_utab() {
    UTab t{};
    for (int r = 0; r < 128; ++r) {
        for (int m = 0; m < 64; ++m) {
            const int l = r >> 1, n = r & 1;
            const double d = (double)(l - m) / 64.0;
            const double u = d * d;
            const double val = n ? u * u : u;
            unsigned off = (unsigned)(r * 128 + m * 2);
            off ^= (off >> 3) & 0x70u;
            t.v[off >> 1] = f2bf_pos(val);
        }
    }
    return t;
}
__device__ const UTab g_U = make_utab();

// ---------------- smem byte offsets -----------------------------------------
#define SM_P    0u          // [128 rows (ii,k)][64 bf16]           16 KB
#define SM_U    16384u      // U: [128 rows l*2+n'][64 bf16]        16 KB
#define SM_TI   32768u      // T: 2 subtiles [64 j][128B], col 2k+n' 16 KB
#define SM_EB   49152u      // [64 l][66 f32]                       16.9 KB
#define SM_CI   66048u      // C: 2 groups x 2 subtiles [64 l][128B] 32 KB
#define SM_LS   98816u      // 2 groups x [64 l][65 f32]            33.3 KB
#define SM_MISC 132096u     // a0inv: 128 f32
#define SMEM_TOTAL 132608u

__device__ __forceinline__ uint32_t sw128(uint32_t o) { return o ^ ((o >> 3) & 0x70u); }

__device__ __forceinline__ uint32_t smem_u32(const void* p) {
    uint32_t a;
    asm("{ .reg .u64 t; cvta.to.shared.u64 t, %1; cvt.u32.u64 %0, t; }" : "=r"(a) : "l"(p));
    return a;
}

// m16n8k16 row.col bf16 -> f32 (sm_80-baseline PTX; HMMA on Blackwell)
__device__ __forceinline__ void mma16816(float acc[4], const uint32_t a[4],
                                         uint32_t b0, uint32_t b1) {
    asm volatile(
        "mma.sync.aligned.m16n8k16.row.col.f32.bf16.bf16.f32 "
        "{%0,%1,%2,%3}, {%4,%5,%6,%7}, {%8,%9}, {%0,%1,%2,%3};"
        : "+f"(acc[0]), "+f"(acc[1]), "+f"(acc[2]), "+f"(acc[3])
        : "r"(a[0]), "r"(a[1]), "r"(a[2]), "r"(a[3]), "r"(b0), "r"(b1));
}

__device__ __forceinline__ void ldmx4(uint32_t r[4], uint32_t addr) {
    asm volatile("ldmatrix.sync.aligned.m8n8.x4.shared.b16 {%0,%1,%2,%3}, [%4];"
                 : "=r"(r[0]), "=r"(r[1]), "=r"(r[2]), "=r"(r[3]) : "r"(addr));
}

#define CP_ASYNC16(dst, src) \
    asm volatile("cp.async.cg.shared.global [%0], [%1], 16;" :: "r"(dst), "l"(src))
#define CP_COMMIT() asm volatile("cp.async.commit_group;")
#define CP_WAIT0()  asm volatile("cp.async.wait_group 0;")
// group barrier: named barrier id (1 or 2), 256 threads
#define BARG(id) asm volatile("bar.sync %0, %1;" :: "r"(id), "r"(256) : "memory")

// ============================================================================
// Main fused kernel (single launch).
// ============================================================================
__global__ void __launch_bounds__(THREADS, 1)
drn_fused(const float* __restrict__ P, const float* __restrict__ weight,
          const float* __restrict__ bias_abs, const float* __restrict__ bias_q,
          const float* __restrict__ lam_abs, const float* __restrict__ lam_q,
          float* __restrict__ out)
{
    extern __shared__ __align__(16) char sm[];
    const uint32_t smb = smem_u32(sm);
    float* a0inv = (float*)(sm + SM_MISC);          // 128 floats

    const int tid = threadIdx.x;
    const int i0  = blockIdx.x * 2;

    // ---- kick off U-table copy (overlaps all setup below) ------------------
    {
        const unsigned char* gp = (const unsigned char*)g_U.v;
        const uint32_t off = (uint32_t)tid * 16;
        CP_ASYNC16(smb + SM_U + off, gp + off);
        CP_ASYNC16(smb + SM_U + off + 8192u, gp + off + 8192u);
        CP_COMMIT();
    }

    // ---- build T: col 2k+n' holds t^(n'+1); one STS.32 per k ---------------
    {
        const int j = tid >> 3, kq = (tid & 7) * 8;
        const float4* wr = (const float4*)(weight + j * 64 + kq);
        const float4 w0 = wr[0], w1 = wr[1];
        const float tv[8] = {-w0.x, -w0.y, -w0.z, -w0.w, -w1.x, -w1.y, -w1.z, -w1.w};
        #pragma unroll
        for (int q = 0; q < 8; ++q) {
            const int k = kq + q;
            const float t = tv[q];
            const uint32_t off = (uint32_t)(k >> 5) * 8192u
                               + (uint32_t)j * 128 + (uint32_t)(k & 31) * 4;
            const __nv_bfloat162 p = __floats2bfloat162_rn(t, t * t);
            *(unsigned*)(sm + SM_TI + sw128(off)) = *(const unsigned*)&p;
        }
    }

    // ---- build EB: thread = (j, 8 l's) --------------------------------------
    {
        const int j = tid >> 3, l0 = (tid & 7) * 8;
        const float bq = bias_q[j], lq = lam_q[j];
        const float ba = bias_abs[j], la = lam_abs[j];
        float* eb = (float*)(sm + SM_EB);
        #pragma unroll
        for (int q = 0; q < 8; ++q) {
            const int l = l0 + q;
            const float sl = (float)l * (1.f / 64.f);
            const float dq = sl - lq, da = sl - la;
            eb[l * 66 + j] = -bq * dq * dq - ba * fabsf(da);
        }
    }

    // ---- fill P tile (bf16) + row sums (4 threads per row) -----------------
    {
        const int r = tid >> 2, qh = tid & 3;
        const float* src = P + ((size_t)(i0 + (r >> 6)) * 64 + (r & 63)) * 64 + qh * 16;
        float s = 0.f;
        #pragma unroll
        for (int q = 0; q < 4; ++q) {
            const float4 f = ((const float4*)src)[q];
            s += f.x + f.y + f.z + f.w;
            const uint32_t off = (uint32_t)r * 128 + (qh * 16 + q * 4) * 2;
            *(__nv_bfloat162*)(sm + SM_P + sw128(off))     = __floats2bfloat162_rn(f.x, f.y);
            *(__nv_bfloat162*)(sm + SM_P + sw128(off + 4)) = __floats2bfloat162_rn(f.z, f.w);
        }
        s += __shfl_xor_sync(0xffffffffu, s, 1);
        s += __shfl_xor_sync(0xffffffffu, s, 2);
        if (qh == 0) a0inv[r] = 1.0f / s;
    }
    CP_WAIT0();
    __syncthreads();   // the ONLY full-CTA barrier; groups diverge after this

    const int lane = tid & 31, wid = tid >> 5;
    const int g = lane >> 2, c = lane & 3;
    const int g2   = wid >> 3;            // warp-group = batch row
    const int barid = 1 + g2;
    const int wid8 = wid & 7;
    const int mw = wid8 & 1, nq = wid8 >> 1;   // M-half (32 k's), N-quarter
    const int mr = g2 * 64 + mw * 32;          // P-row base for GEMM1

    // ldmatrix lane->address maps (relative byte offsets, pre-swizzle)
    const uint32_t aRow = (uint32_t)((lane & 7) + ((lane >> 3) & 1) * 8) * 128
                          + (uint32_t)(lane >> 4) * 16;
    const uint32_t bRow = (uint32_t)((lane & 7) + (lane >> 4) * 8) * 128
                          + (uint32_t)((lane >> 3) & 1) * 16;

    // Hoisted A fragments (P tile rows mr..mr+32)
    uint32_t afr[2][4][4];
    #pragma unroll
    for (int mt = 0; mt < 2; ++mt)
        #pragma unroll
        for (int ks = 0; ks < 4; ++ks)
            ldmx4(afr[mt][ks],
                  smb + SM_P + sw128((uint32_t)(mr + mt * 16) * 128 + aRow + ks * 32));

    // ============ GEMM1: M=64(k) x N=128(l,n') x K=64(m) =====================
    {
        float acc[2][4][4];
        #pragma unroll
        for (int mt = 0; mt < 2; ++mt)
            #pragma unroll
            for (int B = 0; B < 4; ++B)
                acc[mt][B][0] = acc[mt][B][1] = acc[mt][B][2] = acc[mt][B][3] = 0.f;

        #pragma unroll
        for (int ks = 0; ks < 4; ++ks) {
            uint32_t b0[4], b1[4];
            ldmx4(b0, smb + SM_U + sw128((uint32_t)(nq * 32) * 128 + bRow + ks * 32));
            ldmx4(b1, smb + SM_U + sw128((uint32_t)(nq * 32 + 16) * 128 + bRow + ks * 32));
            #pragma unroll
            for (int mt = 0; mt < 2; ++mt) {
                mma16816(acc[mt][0], afr[mt][ks], b0[0], b0[1]);
                mma16816(acc[mt][1], afr[mt][ks], b0[2], b0[3]);
                mma16816(acc[mt][2], afr[mt][ks], b1[0], b1[1]);
                mma16816(acc[mt][3], afr[mt][ks], b1[2], b1[3]);
            }
        }

        // epilogue: M1,M2 are IN-LANE (cols 2c,2c+1 = n'=0,1 at l=nq*16+B*4+c).
        const uint32_t cib = SM_CI + (uint32_t)g2 * 16384u + (uint32_t)mw * 8192u;
        #pragma unroll
        for (int mt = 0; mt < 2; ++mt) {
            const int kg = mw * 32 + mt * 16 + g;       // k index within group
            const float ai_g = a0inv[g2 * 64 + kg];
            const float ai_h = a0inv[g2 * 64 + kg + 8];
            #pragma unroll
            for (int B = 0; B < 4; ++B) {
                const float* a = acc[mt][B];
                const int l = nq * 16 + B * 4 + c;
                const float m1g = a[0] * ai_g, m2g = a[1] * ai_g;
                const float m1h = a[2] * ai_h, m2h = a[3] * ai_h;
                const float c2g = 0.5f * (m2g - m1g * m1g);
                const float c2h = 0.5f * (m2h - m1h * m1h);
                const __nv_bfloat162 pg = __floats2bfloat162_rn(m1g, c2g);
                const __nv_bfloat162 ph = __floats2bfloat162_rn(m1h, c2h);
                const uint32_t offg = (uint32_t)l * 128 + (uint32_t)(kg & 31) * 4;
                *(unsigned*)(sm + cib + sw128(offg))      = *(const unsigned*)&pg;
                *(unsigned*)(sm + cib + sw128(offg + 32)) = *(const unsigned*)&ph;
            }
        }
    }
    BARG(barid);

    // ============ GEMM2: M=64(l) x N=64(j) x K=128(k,n') =====================
    {
        float acc[2][2][4];
        #pragma unroll
        for (int mt = 0; mt < 2; ++mt)
            #pragma unroll
            for (int bk = 0; bk < 2; ++bk)
                acc[mt][bk][0] = acc[mt][bk][1] = acc[mt][bk][2] = acc[mt][bk][3] = 0.f;

        #pragma unroll
        for (int q = 0; q < 8; ++q) {
            const uint32_t s = (uint32_t)q >> 2, ks = (uint32_t)q & 3;
            uint32_t b[4];
            ldmx4(b, smb + SM_TI + s * 8192u
                     + sw128((uint32_t)(nq * 16) * 128 + bRow + ks * 32));
            #pragma unroll
            for (int mt = 0; mt < 2; ++mt) {
                uint32_t a[4];
                ldmx4(a, smb + SM_CI + (uint32_t)g2 * 16384u + s * 8192u
                         + sw128((uint32_t)(mw * 32 + mt * 16) * 128 + aRow + ks * 32));
                mma16816(acc[mt][0], a, b[0], b[1]);
                mma16816(acc[mt][1], a, b[2], b[3]);
            }
        }

        // epilogue: + EB table, stage to group-local LS
        float* ls = (float*)(sm + SM_LS + (uint32_t)g2 * 16640u);
        const float* eb = (const float*)(sm + SM_EB);
        #pragma unroll
        for (int mt = 0; mt < 2; ++mt) {
            const int lA = mw * 32 + mt * 16 + g, lB = lA + 8;
            #pragma unroll
            for (int bk = 0; bk < 2; ++bk) {
                const float* a = acc[mt][bk];
                const int j0 = nq * 16 + bk * 8 + c * 2;
                const float2 eA = *(const float2*)&eb[lA * 66 + j0];
                const float2 eB = *(const float2*)&eb[lB * 66 + j0];
                ls[lA * 65 + j0]     = a[0] + eA.x;
                ls[lA * 65 + j0 + 1] = a[1] + eA.y;
                ls[lB * 65 + j0]     = a[2] + eB.x;
                ls[lB * 65 + j0 + 1] = a[3] + eB.y;
            }
        }
    }
    BARG(barid);

    // ====== softmax over l (group-local; no max pass, |logits| <= ~4) =======
    {
        const float* ls = (const float*)(sm + SM_LS + (uint32_t)g2 * 16640u);
        const int tl = tid & 255;
        const int j = tl >> 2, h = tl & 3;
        float v[16], s = 0.f;
        #pragma unroll
        for (int q = 0; q < 16; ++q) {
            v[q] = __expf(ls[(h * 16 + q) * 65 + j]);
            s += v[q];
        }
        s += __shfl_xor_sync(0xffffffffu, s, 1);
        s += __shfl_xor_sync(0xffffffffu, s, 2);
        const float inv = 1.0f / s;
        float4* ob = (float4*)(out + ((size_t)(i0 + g2) * 64 + j) * 64 + h * 16);
        #pragma unroll
        for (int q = 0; q < 4; ++q)
            ob[q] = make_float4(v[4 * q] * inv, v[4 * q + 1] * inv,
                                v[4 * q + 2] * inv, v[4 * q + 3] * inv);
    }
}

// ---------------------------------------------------------------------------
extern "C" void kernel_launch(void* const* d_in, const int* in_sizes, int n_in,
                              void* d_out, int out_size)
{
    const float* P        = (const float*)d_in[0];
    const float* weight   = (const float*)d_in[1];
    const float* bias_abs = (const float*)d_in[2];
    const float* bias_q   = (const float*)d_in[3];
    const float* lam_abs  = (const float*)d_in[4];
    const float* lam_q    = (const float*)d_in[5];
    float* out = (float*)d_out;

    cudaFuncSetAttribute(drn_fused, cudaFuncAttributeMaxDynamicSharedMemorySize,
                         SMEM_TOTAL);
    drn_fused<<<128, THREADS, SMEM_TOTAL>>>(P, weight, bias_abs, bias_q,
                                            lam_abs, lam_q, out);
}